// round 11
// baseline (speedup 1.0000x reference)
#include <cuda_runtime.h>

// out[n, d, t] = mean over d' of in[n, d', t]
// in: [32768, 64, 64] fp32. Compulsory traffic: 512MB read + 512MB write.
//
// R10 finding: st.global.wt (write-through, no L2 write-allocate) gave the
// first real bench win (172.3 -> 169.3us; prior spread 172.3-173.2). This
// round tests the symmetric load knob: ld.global.cv (no L2 allocation on
// reads). Both streams touch every line exactly once, so L2 allocation is
// pure tag/slot overhead in both directions.

static constexpr int N_AGENTS = 32768;
static constexpr int FEAT_DIM = 64;
static constexpr int QUADS_PER_ROW = 16;   // 64 t / 4
static constexpr int F4_PER_AGENT = 1024;  // 64*64/4

__global__ void __launch_bounds__(256)
mean_bcast_kernel(const float4* __restrict__ in, float4* __restrict__ out) {
    int gid = blockIdx.x * blockDim.x + threadIdx.x;   // 0 .. 32768*16-1
    int agent = gid >> 4;
    int tq = gid & 15;

    const float4* __restrict__ row = in + (size_t)agent * F4_PER_AGENT + tq;
    float4* __restrict__ orow = out + (size_t)agent * F4_PER_AGENT + tq;

    float ax = 0.f, ay = 0.f, az = 0.f, aw = 0.f;
    #pragma unroll 16
    for (int d = 0; d < FEAT_DIM; d++) {
        float4 v = __ldcv(&row[d * QUADS_PER_ROW]);
        ax += v.x; ay += v.y; az += v.z; aw += v.w;
    }
    const float inv = 1.0f / (float)FEAT_DIM;
    float4 m;
    m.x = ax * inv; m.y = ay * inv; m.z = az * inv; m.w = aw * inv;

    #pragma unroll 16
    for (int d = 0; d < FEAT_DIM; d++) {
        __stwt(&orow[d * QUADS_PER_ROW], m);
    }
}

extern "C" void kernel_launch(void* const* d_in, const int* in_sizes, int n_in,
                              void* d_out, int out_size) {
    const float4* in = (const float4*)d_in[0];
    float4* out = (float4*)d_out;
    // seq_start_end (d_in[1]) is a no-op: contiguous partition, mean is per-agent.
    int total_threads = N_AGENTS * QUADS_PER_ROW;   // 524288
    int block = 256;
    int grid = total_threads / block;               // 2048
    mean_bcast_kernel<<<grid, block>>>(in, out);
}

// round 12
// speedup vs baseline: 1.0154x; 1.0154x over previous
#include <cuda_runtime.h>

// out[n, d, t] = mean over d' of in[n, d', t]
// in: [32768, 64, 64] fp32. Compulsory traffic: 512MB read + 512MB write.
//
// FINAL config (R10, reproduced here): __ldcs loads + __stwt stores.
// Cache-policy matrix fully measured:
//   ld.cs + st.cs : 172.3-173.2us (5 runs)
//   ld.cs + st.wt : 169.3us      <- best (write-through skips L2
//                                   write-allocate/dirty-writeback churn)
//   ld.cv + st.wt : 171.3us      (cv loses LTS read-combining)
// All structural variants regress (persistent grid -4%, phase split -6%,
// half-threads -34%); block 128/256/512 and unroll 8/16 neutral.
// 2048 x 256 = 524288 threads (full latency-hiding complement),
// 16 threads/agent, one float4/thread, fully-coalesced 256B segments.

static constexpr int N_AGENTS = 32768;
static constexpr int FEAT_DIM = 64;
static constexpr int QUADS_PER_ROW = 16;   // 64 t / 4
static constexpr int F4_PER_AGENT = 1024;  // 64*64/4

__global__ void __launch_bounds__(256)
mean_bcast_kernel(const float4* __restrict__ in, float4* __restrict__ out) {
    int gid = blockIdx.x * blockDim.x + threadIdx.x;   // 0 .. 32768*16-1
    int agent = gid >> 4;
    int tq = gid & 15;

    const float4* __restrict__ row = in + (size_t)agent * F4_PER_AGENT + tq;
    float4* __restrict__ orow = out + (size_t)agent * F4_PER_AGENT + tq;

    float ax = 0.f, ay = 0.f, az = 0.f, aw = 0.f;
    #pragma unroll 16
    for (int d = 0; d < FEAT_DIM; d++) {
        float4 v = __ldcs(&row[d * QUADS_PER_ROW]);
        ax += v.x; ay += v.y; az += v.z; aw += v.w;
    }
    const float inv = 1.0f / (float)FEAT_DIM;
    float4 m;
    m.x = ax * inv; m.y = ay * inv; m.z = az * inv; m.w = aw * inv;

    #pragma unroll 16
    for (int d = 0; d < FEAT_DIM; d++) {
        __stwt(&orow[d * QUADS_PER_ROW], m);
    }
}

extern "C" void kernel_launch(void* const* d_in, const int* in_sizes, int n_in,
                              void* d_out, int out_size) {
    const float4* in = (const float4*)d_in[0];
    float4* out = (float4*)d_out;
    // seq_start_end (d_in[1]) is a no-op: contiguous partition, mean is per-agent.
    int total_threads = N_AGENTS * QUADS_PER_ROW;   // 524288
    int block = 256;
    int grid = total_threads / block;               // 2048
    mean_bcast_kernel<<<grid, block>>>(in, out);
}

// round 13
// speedup vs baseline: 1.0171x; 1.0017x over previous
#include <cuda_runtime.h>

// out[n, d, t] = mean over d' of in[n, d', t]
// in: [32768, 64, 64] fp32. Compulsory traffic: 512MB read + 512MB write.
//
// FINAL (confirmed champion, R10+R12: 169.3 / 168.7us): __ldcs + __stwt.
// Cache-policy matrix fully measured:
//   ld.cs + st.cs : 172.3-173.2us (5 runs)
//   ld.cs + st.wt : 168.7-169.3us <- best (write-through skips L2
//                                   write-allocate/dirty-writeback churn)
//   ld.cv + st.wt : 171.3us      (cv loses LTS read-combining)
// Structural variants all regress (persistent grid -4%, phase split -6%,
// half-threads/2x-footprint -34%); block 128/256/512, unroll 8/16 neutral.
// TMA offers nothing: LTS throughput cap (~6300 B/cyc) is path-independent.
// Kernel runs at the B300 mixed-stream memory roofline: 1.0737GB at
// ~6.7TB/s effective, issue 4.3%, all compute pipes idle.
//
// Layout: 2048 x 256 = 524288 threads (full latency-hiding complement),
// 16 threads/agent, one float4/thread, d-loop stride 256B ->
// fully-coalesced segments per half-warp.

static constexpr int N_AGENTS = 32768;
static constexpr int FEAT_DIM = 64;
static constexpr int QUADS_PER_ROW = 16;   // 64 t / 4
static constexpr int F4_PER_AGENT = 1024;  // 64*64/4

__global__ void __launch_bounds__(256)
mean_bcast_kernel(const float4* __restrict__ in, float4* __restrict__ out) {
    int gid = blockIdx.x * blockDim.x + threadIdx.x;   // 0 .. 32768*16-1
    int agent = gid >> 4;
    int tq = gid & 15;

    const float4* __restrict__ row = in + (size_t)agent * F4_PER_AGENT + tq;
    float4* __restrict__ orow = out + (size_t)agent * F4_PER_AGENT + tq;

    float ax = 0.f, ay = 0.f, az = 0.f, aw = 0.f;
    #pragma unroll 16
    for (int d = 0; d < FEAT_DIM; d++) {
        float4 v = __ldcs(&row[d * QUADS_PER_ROW]);
        ax += v.x; ay += v.y; az += v.z; aw += v.w;
    }
    const float inv = 1.0f / (float)FEAT_DIM;
    float4 m;
    m.x = ax * inv; m.y = ay * inv; m.z = az * inv; m.w = aw * inv;

    #pragma unroll 16
    for (int d = 0; d < FEAT_DIM; d++) {
        __stwt(&orow[d * QUADS_PER_ROW], m);
    }
}

extern "C" void kernel_launch(void* const* d_in, const int* in_sizes, int n_in,
                              void* d_out, int out_size) {
    const float4* in = (const float4*)d_in[0];
    float4* out = (float4*)d_out;
    // seq_start_end (d_in[1]) is a no-op: contiguous partition, mean is per-agent.
    int total_threads = N_AGENTS * QUADS_PER_ROW;   // 524288
    int block = 256;
    int grid = total_threads / block;               // 2048
    mean_bcast_kernel<<<grid, block>>>(in, out);
}